// round 1
// baseline (speedup 1.0000x reference)
#include <cuda_runtime.h>

#define NBINS 64
#define NT 128              // threads per block (hist kernel)
#define BLOCKS_PER_IMG 12
#define NIMG 48             // 2 tensors * 8 batch * 3 channels
#define IMG_PIX 65536       // 256*256
#define WIN 6               // window half-width in bins

// global accumulation buffers (no cudaMalloc allowed)
__device__ float g_hist[NIMG * NBINS];

__global__ void zero_kernel() {
    int i = blockIdx.x * blockDim.x + threadIdx.x;
    if (i < NIMG * NBINS) g_hist[i] = 0.0f;
}

__global__ __launch_bounds__(NT) void hist_kernel(const float* __restrict__ pred,
                                                  const float* __restrict__ tgt) {
    // per-thread private histogram columns: hist[bin*NT + tid]
    // bank = (bin*128 + tid) % 32 = tid % 32  -> conflict-free for any bin per lane
    __shared__ float sh[NBINS * NT];
    __shared__ float psum[NBINS * 2];

    const int tid = threadIdx.x;
    const int img = blockIdx.x / BLOCKS_PER_IMG;
    const int blk = blockIdx.x % BLOCKS_PER_IMG;

    const float* src = (img < 24) ? pred : tgt;
    const int cimg   = (img < 24) ? img : img - 24;
    const float4* base = (const float4*)(src + (size_t)cimg * IMG_PIX);

    // work units of NT*4 = 512 pixels; 128 units per image
    const int units_total = IMG_PIX / (NT * 4);
    const int u0 = (blk    ) * units_total / BLOCKS_PER_IMG;
    const int u1 = (blk + 1) * units_total / BLOCKS_PER_IMG;

    #pragma unroll
    for (int b = 0; b < NBINS; b++) sh[b * NT + tid] = 0.0f;
    __syncthreads();

    // Gaussian soft-assignment constants.
    // w_j = exp(-A*(x - j/63)^2), A = 1/(2*bin_width^2) = 2048, Delta = 1/63.
    // Recurrence: w_{k+1} = w_k * s,  s_{k+1} = s_k * v^2,
    //   s_start = u*v (up) or (1/u)*v (down),
    //   u = exp(2*A*Delta*d0), v = exp(-A*Delta^2).
    const float A   = 2048.0f;
    const float DLT = 1.0f / 63.0f;
    const float C   = 4096.0f / 63.0f;         // 2*A*Delta
    const float v   = __expf(-A * DLT * DLT);  // constant, folded/hoisted
    const float v2  = v * v;

    float* h = sh + tid;

    for (int u = u0; u < u1; u++) {
        float4 xv = base[(size_t)u * NT + tid];
        #pragma unroll
        for (int c = 0; c < 4; c++) {
            float x = (c == 0) ? xv.x : (c == 1) ? xv.y : (c == 2) ? xv.z : xv.w;
            int j0 = __float2int_rn(x * 63.0f);
            j0 = max(0, min(63, j0));
            float d0 = fmaf(-(float)j0, DLT, x);        // x - c_{j0}, |d0| <= ~Delta/2
            float w0 = __expf(-A * d0 * d0);
            float eu = __expf( C * d0);
            float ed = __expf(-C * d0);

            h[j0 * NT] += w0;

            float w = w0, s = eu * v;
            #pragma unroll
            for (int k = 1; k <= WIN; k++) {
                w *= s; s *= v2;
                int j = j0 + k;
                if (j < NBINS) h[j * NT] += w;
            }
            w = w0; s = ed * v;
            #pragma unroll
            for (int k = 1; k <= WIN; k++) {
                w *= s; s *= v2;
                int j = j0 - k;
                if (j >= 0) h[j * NT] += w;
            }
        }
    }
    __syncthreads();

    // Reduce thread columns. Thread t: bin = t&63, half = t>>6 sums 64 columns.
    // Lane-staggered start index keeps banks distinct (bank = ((i+tid)&63)%32).
    {
        int bin  = tid & 63;
        int part = tid >> 6;          // 0..1
        int cbase = part * 64;
        float acc = 0.0f;
        #pragma unroll
        for (int i = 0; i < 64; i++) {
            int col = cbase + ((i + tid) & 63);
            acc += sh[bin * NT + col];
        }
        psum[part * 64 + bin] = acc;
    }
    __syncthreads();
    if (tid < NBINS) {
        float tot = psum[tid] + psum[64 + tid];
        atomicAdd(&g_hist[img * NBINS + tid], tot);
    }
}

__global__ void finalize_kernel(float* __restrict__ out) {
    __shared__ float sums[NIMG];
    __shared__ float accs[24];
    int t = threadIdx.x;

    if (t < NIMG) {
        float s = 0.0f;
        #pragma unroll
        for (int b = 0; b < NBINS; b++) s += g_hist[t * NBINS + b];
        sums[t] = s;
    }
    __syncthreads();

    if (t < 24) {
        float rp = 1.0f / (sums[t]      + 1e-7f);
        float rt = 1.0f / (sums[24 + t] + 1e-7f);
        float cp = 0.0f, ct = 0.0f, acc = 0.0f;
        #pragma unroll
        for (int b = 0; b < NBINS; b++) {
            cp += g_hist[t * NBINS + b] * rp;
            ct += g_hist[(24 + t) * NBINS + b] * rt;
            acc += fabsf(cp - ct);
        }
        accs[t] = acc;
    }
    __syncthreads();

    if (t == 0) {
        float s = 0.0f;
        #pragma unroll
        for (int c = 0; c < 24; c++) s += accs[c];
        out[0] = s * (1.0f / 1536.0f);   // mean over (8,3,64)
    }
}

extern "C" void kernel_launch(void* const* d_in, const int* in_sizes, int n_in,
                              void* d_out, int out_size) {
    const float* pred = (const float*)d_in[0];
    const float* tgt  = (const float*)d_in[1];
    float* out        = (float*)d_out;

    zero_kernel<<<(NIMG * NBINS + 255) / 256, 256>>>();
    hist_kernel<<<NIMG * BLOCKS_PER_IMG, NT>>>(pred, tgt);
    finalize_kernel<<<1, 64>>>(out);
}

// round 2
// speedup vs baseline: 1.2055x; 1.2055x over previous
#include <cuda_runtime.h>

#define NBINS 64
#define NT 128              // threads per block (hist kernel)
#define BPI 15              // blocks per image
#define NIMG 48             // 2 tensors * 8 batch * 3 channels
#define IMG_PIX 65536       // 256*256
#define IMG_F4 16384        // float4 elements per image
#define WIN 5               // window half-width in bins (tail < 2.5e-6)
#define NROW (NBINS + 2*WIN)  // 74 rows: bins -5..68 (guard bins absorb OOB)
#define NBLK (NIMG * BPI)   // 720

// per-block partial histograms; every entry written unconditionally each call
__device__ float g_part[NBLK * NBINS];

__global__ __launch_bounds__(NT) void hist_kernel(const float* __restrict__ pred,
                                                  const float* __restrict__ tgt) {
    // per-thread private histogram columns: sh[row*NT + tid]
    // bank = tid % 32 for every row -> conflict-free for any per-lane bin
    __shared__ float sh[NROW * NT];      // 37,888 B
    __shared__ float psum[2 * NBINS];

    const int tid = threadIdx.x;
    const int img = blockIdx.x / BPI;
    const int blk = blockIdx.x % BPI;

    const float* src = (img < 24) ? pred : tgt;
    const int cimg   = (img < 24) ? img : img - 24;
    const float4* base = (const float4*)(src + (size_t)cimg * IMG_PIX);

    const int f0 = (blk    ) * IMG_F4 / BPI;
    const int f1 = (blk + 1) * IMG_F4 / BPI;

    for (int i = tid; i < NROW * NT; i += NT) sh[i] = 0.0f;
    __syncthreads();

    // Gaussian soft-assignment, geometric recurrence:
    // w_k = w0 * eu^k * v^(k^2),  eu = exp(C*d0), v = exp(-A*DLT^2)
    const float A   = 2048.0f;          // 1/(2*bin_width^2)
    const float DLT = 1.0f / 63.0f;
    const float C   = 4096.0f / 63.0f;  // 2*A*DLT
    const float v   = __expf(-A * DLT * DLT);
    const float v2  = v * v;

    for (int i = f0 + tid; i < f1; i += NT) {
        float4 xv = base[i];
        #pragma unroll
        for (int c = 0; c < 4; c++) {
            float x = (c == 0) ? xv.x : (c == 1) ? xv.y : (c == 2) ? xv.z : xv.w;
            int j0 = __float2int_rn(x * 63.0f);
            j0 = max(0, min(63, j0));
            float d0 = fmaf(-(float)j0, DLT, x);      // x - j0/63
            float w0 = __expf(-A * d0 * d0);
            float eu = __expf( C * d0);
            float ed = __expf(-C * d0);

            float* h = sh + (j0 + WIN) * NT + tid;    // immediate-offset RMWs
            h[0] += w0;

            float w = w0, s = eu * v;
            #pragma unroll
            for (int k = 1; k <= WIN; k++) {
                w *= s; s *= v2;
                h[k * NT] += w;
            }
            w = w0; s = ed * v;
            #pragma unroll
            for (int k = 1; k <= WIN; k++) {
                w *= s; s *= v2;
                h[-k * NT] += w;
            }
        }
    }
    __syncthreads();

    // Reduce 128 thread-columns. thread t: bin = t&63, half = t>>6 sums 64 cols.
    // Lane-staggered start keeps banks distinct.
    {
        int bin  = tid & 63;
        int part = tid >> 6;
        int cbase = part * 64;
        const float* row = sh + (bin + WIN) * NT;
        float acc = 0.0f;
        #pragma unroll
        for (int i = 0; i < 64; i++) {
            acc += row[cbase + ((i + tid) & 63)];
        }
        psum[part * 64 + bin] = acc;
    }
    __syncthreads();
    if (tid < NBINS) {
        g_part[blockIdx.x * NBINS + tid] = psum[tid] + psum[64 + tid];
    }
}

#define FT 1024
#define HROW 65   // padded row stride to avoid bank conflicts in cumsum phase

__global__ __launch_bounds__(FT) void finalize_kernel(float* __restrict__ out) {
    __shared__ float hist[NIMG * HROW];   // 12,480 B
    __shared__ float accs[24];
    int t = threadIdx.x;

    // sum the BPI per-block partials for each (img, bin)
    for (int p = t; p < NIMG * NBINS; p += FT) {
        int img = p >> 6, bin = p & 63;
        float s = 0.0f;
        #pragma unroll
        for (int b = 0; b < BPI; b++)
            s += g_part[(img * BPI + b) * NBINS + bin];
        hist[img * HROW + bin] = s;
    }
    __syncthreads();

    if (t < 24) {
        const float* hp = hist + t * HROW;
        const float* ht = hist + (24 + t) * HROW;
        float sp = 0.0f, st = 0.0f;
        #pragma unroll
        for (int b = 0; b < NBINS; b++) { sp += hp[b]; st += ht[b]; }
        float rp = 1.0f / (sp + 1e-7f);
        float rt = 1.0f / (st + 1e-7f);
        float cp = 0.0f, ct = 0.0f, acc = 0.0f;
        #pragma unroll
        for (int b = 0; b < NBINS; b++) {
            cp += hp[b] * rp;
            ct += ht[b] * rt;
            acc += fabsf(cp - ct);
        }
        accs[t] = acc;
    }
    __syncthreads();

    if (t == 0) {
        float s = 0.0f;
        #pragma unroll
        for (int c = 0; c < 24; c++) s += accs[c];
        out[0] = s * (1.0f / 1536.0f);   // mean over (8,3,64)
    }
}

extern "C" void kernel_launch(void* const* d_in, const int* in_sizes, int n_in,
                              void* d_out, int out_size) {
    const float* pred = (const float*)d_in[0];
    const float* tgt  = (const float*)d_in[1];
    float* out        = (float*)d_out;

    hist_kernel<<<NBLK, NT>>>(pred, tgt);
    finalize_kernel<<<1, FT>>>(out);
}